// round 6
// baseline (speedup 1.0000x reference)
#include <cuda_runtime.h>
#include <cstdint>

// Gumbel-Sinkhorn, B=16, N=256, TAU=0.1, up to 100 iterations.
//
// Primal Sinkhorn-Knopp on the constant matrix E = exp(a/tau - m):
//   e[i] = 1 / sum_j E[i][j] * d[j]     (row normalize)
//   d[j] = 1 / sum_i E[i][j] * e[i]     (col normalize)
//   out  = E[i][j] * e[i] * d[j]
// E lives in registers, split across an 8-CTA cluster (32 rows per CTA).
// Exchange: 8x 1KB cp.async.bulk (SMEM -> peer SMEM) + one mbarrier wait.
// R6: early convergence exit (converged iterations are identity in the
// reference too; all CTAs of a cluster compute bitwise-identical colsums so
// the break is uniform), expect_tx hoisted off the critical path, bulk sends
// issued by 8 threads in parallel.

namespace {
constexpr int NMAT    = 16;
constexpr int N       = 256;
constexpr int CSZ     = 8;           // cluster size (CTAs per matrix)
constexpr int ROWS    = N / CSZ;     // 32 rows per CTA
constexpr int THREADS = 1024;
constexpr int NWARP   = THREADS / 32;
constexpr int NITER   = 100;
constexpr float INV_TAU = 10.0f;
constexpr float CVG_EPS = 1e-6f;     // matches torch early-exit tolerance
constexpr unsigned SLICE_BYTES = N * 4;              // 1024 B per source CTA
constexpr unsigned TX_BYTES    = SLICE_BYTES * CSZ;  // 8192 B per iter received
}

__device__ __forceinline__ uint32_t smem_u32(const void* p) {
    return (uint32_t)__cvta_generic_to_shared(p);
}

__device__ __forceinline__ uint32_t mapa_rank(uint32_t laddr, uint32_t rank) {
    uint32_t rem;
    asm volatile("mapa.shared::cluster.u32 %0, %1, %2;" : "=r"(rem) : "r"(laddr), "r"(rank));
    return rem;
}

// Plain remote store (prologue max-exchange only).
__device__ __forceinline__ void st_cluster_f32(uint32_t laddr, uint32_t rank, float v) {
    uint32_t rem = mapa_rank(laddr, rank);
    asm volatile("st.shared::cluster.f32 [%0], %1;" :: "r"(rem), "f"(v) : "memory");
}

// 1KB bulk copy: local SMEM -> (possibly remote) cluster SMEM, completion as
// a single complete_tx at the destination CTA's mbarrier.
__device__ __forceinline__ void bulk_s2s(uint32_t dst_cluster, uint32_t src_local,
                                         uint32_t bytes, uint32_t mbar_cluster) {
    asm volatile(
        "cp.async.bulk.shared::cluster.shared::cta.mbarrier::complete_tx::bytes "
        "[%0], [%1], %2, [%3];"
        :: "r"(dst_cluster), "r"(src_local), "r"(bytes), "r"(mbar_cluster) : "memory");
}

__device__ __forceinline__ void mbar_expect_tx(uint32_t addr, uint32_t bytes) {
    asm volatile("mbarrier.arrive.expect_tx.shared.b64 _, [%0], %1;"
                 :: "r"(addr), "r"(bytes) : "memory");
}

__device__ __forceinline__ void mbar_wait(uint32_t addr, uint32_t phase) {
    asm volatile(
        "{\n\t"
        ".reg .pred P;\n\t"
        "WLOOP_%=:\n\t"
        "mbarrier.try_wait.parity.acquire.cluster.shared::cta.b64 P, [%0], %1, 0x989680;\n\t"
        "@P bra WDONE_%=;\n\t"
        "bra WLOOP_%=;\n\t"
        "WDONE_%=:\n\t"
        "}"
        :: "r"(addr), "r"(phase) : "memory");
}

__device__ __forceinline__ void cluster_sync_all() {
    asm volatile("barrier.cluster.arrive.aligned;" ::: "memory");
    asm volatile("barrier.cluster.wait.aligned;" ::: "memory");
}

__global__ void __launch_bounds__(THREADS, 1) __cluster_dims__(CSZ, 1, 1)
sinkhorn_kernel(const float* __restrict__ A, float* __restrict__ Out)
{
    __shared__ __align__(16) float d_vec[N];
    __shared__ __align__(16) float e_vec[ROWS];
    // receive buffers: [parity][source rank][col]  (bulk copies land here)
    __shared__ __align__(16) float xbuf[2][CSZ][N];
    // staging buffer for my 256 column partials: [parity][col]
    __shared__ __align__(16) float pbuf[2][N];
    __shared__ __align__(8) unsigned long long mbar[2];
    __shared__ float red_sh[NWARP];
    __shared__ float mbuf[CSZ];
    __shared__ __align__(16) float cvg_sh[8];   // per-warp max |colsum-1|

    const int tid  = threadIdx.x;
    const int w    = tid >> 5;
    const int l    = tid & 31;
    const int rank = blockIdx.x & (CSZ - 1);
    const int b    = blockIdx.x >> 3;

    const float* Am = A   + (size_t)b * N * N;
    float*       Om = Out + (size_t)b * N * N;

    if (tid == 0) {
        asm volatile("mbarrier.init.shared.b64 [%0], 1;" :: "r"(smem_u32(&mbar[0])) : "memory");
        asm volatile("mbarrier.init.shared.b64 [%0], 1;" :: "r"(smem_u32(&mbar[1])) : "memory");
        asm volatile("fence.mbarrier_init.release.cluster;" ::: "memory");
    }

    // ---- row layout: warp w owns global row (rank*32 + w), lane l owns cols [8l, 8l+8)
    const int grow = rank * ROWS + w;
    const int c0   = l * 8;

    float ar[8];
    {
        float4 a0 = *(const float4*)(Am + grow * N + c0);
        float4 a1 = *(const float4*)(Am + grow * N + c0 + 4);
        ar[0] = a0.x; ar[1] = a0.y; ar[2] = a0.z; ar[3] = a0.w;
        ar[4] = a1.x; ar[5] = a1.y; ar[6] = a1.z; ar[7] = a1.w;
        #pragma unroll
        for (int k = 0; k < 8; k++) ar[k] *= INV_TAU;
    }

    // ---- col layout: thread t = 4*j + g owns column j, local rows [8g, 8g+8)
    const int jc = tid >> 2;
    const int g  = tid & 3;
    float ac[8];
    #pragma unroll
    for (int k = 0; k < 8; k++)
        ac[k] = Am[(rank * ROWS + g * 8 + k) * N + jc] * INV_TAU;

    // ---- global per-matrix max m (for stable E = exp(a/tau - m))
    float mx = ar[0];
    #pragma unroll
    for (int k = 1; k < 8; k++) mx = fmaxf(mx, ar[k]);
    #pragma unroll
    for (int off = 16; off; off >>= 1)
        mx = fmaxf(mx, __shfl_xor_sync(0xffffffffu, mx, off));
    if (l == 0) red_sh[w] = mx;
    __syncthreads();
    if (w == 0) {
        float v = red_sh[l];
        #pragma unroll
        for (int off = 16; off; off >>= 1)
            v = fmaxf(v, __shfl_xor_sync(0xffffffffu, v, off));
        if (l == 0) {
            uint32_t slot = smem_u32(&mbuf[rank]);
            #pragma unroll
            for (int r = 0; r < CSZ; r++) st_cluster_f32(slot, r, v);
        }
    }
    cluster_sync_all();   // orders mbuf stores AND mbarrier inits cluster-wide
    float m = mbuf[0];
    #pragma unroll
    for (int r = 1; r < CSZ; r++) m = fmaxf(m, mbuf[r]);

    // ---- E chunks in registers (both layouts)
    float er[8], ec[8];
    #pragma unroll
    for (int k = 0; k < 8; k++) er[k] = __expf(ar[k] - m);
    #pragma unroll
    for (int k = 0; k < 8; k++) ec[k] = __expf(ac[k] - m);

    if (tid < N) d_vec[tid] = 1.0f;   // c = 0 initially
    if (w == 0 && l < 8) cvg_sh[l] = 1.0f;
    __syncthreads();

    // ---- precomputed cluster addresses
    const uint32_t xb_local = smem_u32(&xbuf[0][0][0]);
    const uint32_t mb_local = smem_u32(&mbar[0]);
    const uint32_t pb_local = smem_u32(&pbuf[0][0]);
    // thread tid<8 sends to rank tid
    uint32_t rxb_t = 0, rmb_t = 0;
    if (tid < CSZ) {
        rxb_t = mapa_rank(xb_local, (uint32_t)tid);
        rmb_t = mapa_rank(mb_local, (uint32_t)tid);
    }
    const uint32_t my_slice_off = (uint32_t)rank * SLICE_BYTES;

    #pragma unroll 1
    for (int it = 0; it < NITER; it++) {
        const uint32_t par = (uint32_t)(it & 1);

        // post expectation early: off the critical path (negative tx is legal)
        if (tid == 0)
            mbar_expect_tx(mb_local + par * 8, TX_BYTES);

        // ======== row pass: rowsum_i = sum_j E[i][j] * d[j] ========
        float4 d0 = *(const float4*)&d_vec[c0];
        float4 d1 = *(const float4*)&d_vec[c0 + 4];
        float s = er[0]*d0.x + er[1]*d0.y + er[2]*d0.z + er[3]*d0.w
                + er[4]*d1.x + er[5]*d1.y + er[6]*d1.z + er[7]*d1.w;
        #pragma unroll
        for (int off = 16; off; off >>= 1)
            s += __shfl_xor_sync(0xffffffffu, s, off);
        if (l == 0) e_vec[w] = __fdividef(1.0f, fmaxf(s, 1e-30f));
        __syncthreads();

        // ======== col pass: partial_j = sum_{local i} E[i][j] * e[i] ========
        float4 e0 = *(const float4*)&e_vec[g * 8];
        float4 e1 = *(const float4*)&e_vec[g * 8 + 4];
        float p = ec[0]*e0.x + ec[1]*e0.y + ec[2]*e0.z + ec[3]*e0.w
                + ec[4]*e1.x + ec[5]*e1.y + ec[6]*e1.z + ec[7]*e1.w;
        p += __shfl_xor_sync(0xffffffffu, p, 1);
        p += __shfl_xor_sync(0xffffffffu, p, 2);
        if (g == 0) pbuf[par][jc] = p;
        __syncthreads();   // pbuf[par] complete

        // ======== bulk exchange: 1KB to each cluster CTA (8 parallel issuers) ====
        if (tid < CSZ) {
            asm volatile("fence.proxy.async.shared::cta;" ::: "memory");
            uint32_t src  = pb_local + par * SLICE_BYTES;
            uint32_t doff = par * (CSZ * SLICE_BYTES) + my_slice_off;
            bulk_s2s(rxb_t + doff, src, SLICE_BYTES, rmb_t + par * 8);
        }

        // ======== combine 8 partials -> d[j] + convergence stat ========
        if (tid < N) {
            mbar_wait(mb_local + par * 8, (uint32_t)((it >> 1) & 1));
            float f = xbuf[par][0][tid];
            #pragma unroll
            for (int r = 1; r < CSZ; r++) f += xbuf[par][r][tid];
            d_vec[tid] = __fdividef(1.0f, fmaxf(f, 1e-30f));
            // colsum deviation (identical in every CTA -> uniform break)
            float dev = fabsf(f - 1.0f);
            #pragma unroll
            for (int off = 16; off; off >>= 1)
                dev = fmaxf(dev, __shfl_xor_sync(0xffffffffu, dev, off));
            if (l == 0) cvg_sh[w] = dev;
        }
        __syncthreads();

        // uniform early exit once converged (remaining iterations are identity)
        float4 cv0 = *(const float4*)&cvg_sh[0];
        float4 cv1 = *(const float4*)&cvg_sh[4];
        float cmax = fmaxf(fmaxf(fmaxf(cv0.x, cv0.y), fmaxf(cv0.z, cv0.w)),
                           fmaxf(fmaxf(cv1.x, cv1.y), fmaxf(cv1.z, cv1.w)));
        if (cmax < CVG_EPS) break;
    }

    // ======== epilogue: P = E * e[i] * d[j] ========
    {
        float ev = e_vec[w];
        float4 d0 = *(const float4*)&d_vec[c0];
        float4 d1 = *(const float4*)&d_vec[c0 + 4];
        float4 o0, o1;
        o0.x = er[0] * ev * d0.x;  o0.y = er[1] * ev * d0.y;
        o0.z = er[2] * ev * d0.z;  o0.w = er[3] * ev * d0.w;
        o1.x = er[4] * ev * d1.x;  o1.y = er[5] * ev * d1.y;
        o1.z = er[6] * ev * d1.z;  o1.w = er[7] * ev * d1.w;
        *(float4*)(Om + grow * N + c0)     = o0;
        *(float4*)(Om + grow * N + c0 + 4) = o1;
    }

    // keep all CTAs alive until every in-flight bulk copy has been consumed
    cluster_sync_all();
}

extern "C" void kernel_launch(void* const* d_in, const int* in_sizes, int n_in,
                              void* d_out, int out_size) {
    const float* alpha = (const float*)d_in[0];
    float* out = (float*)d_out;
    sinkhorn_kernel<<<NMAT * CSZ, THREADS>>>(alpha, out);
}

// round 7
// speedup vs baseline: 2.3588x; 2.3588x over previous
#include <cuda_runtime.h>
#include <cstdint>

// Gumbel-Sinkhorn, B=16, N=256, TAU=0.1, 100 iterations.
//
// Primal Sinkhorn-Knopp on the constant matrix E = exp(a/tau - m):
//   e[i] = 1 / sum_j E[i][j] * d[j]     (row normalize)
//   d[j] = 1 / sum_i E[i][j] * e[i]     (col normalize)
//   out  = E[i][j] * e[i] * d[j]
// R7: 4-CTA cluster (64 rows per CTA), E in registers in both row and col
// layouts (32 regs/thread). Exchange = 4x 1KB cp.async.bulk (SMEM -> peer
// SMEM, single complete_tx per copy) + one mbarrier parity wait per iter.
// No convergence check (R6 showed it never fires and costs 1.5K cyc/iter).

namespace {
constexpr int NMAT    = 16;
constexpr int N       = 256;
constexpr int CSZ     = 4;           // cluster size (CTAs per matrix)
constexpr int ROWS    = N / CSZ;     // 64 rows per CTA
constexpr int THREADS = 1024;
constexpr int NWARP   = THREADS / 32;
constexpr int NITER   = 100;
constexpr float INV_TAU = 10.0f;
constexpr unsigned SLICE_BYTES = N * 4;              // 1024 B per source CTA
constexpr unsigned TX_BYTES    = SLICE_BYTES * CSZ;  // 4096 B per iter received
}

__device__ __forceinline__ uint32_t smem_u32(const void* p) {
    return (uint32_t)__cvta_generic_to_shared(p);
}

__device__ __forceinline__ uint32_t mapa_rank(uint32_t laddr, uint32_t rank) {
    uint32_t rem;
    asm volatile("mapa.shared::cluster.u32 %0, %1, %2;" : "=r"(rem) : "r"(laddr), "r"(rank));
    return rem;
}

// Plain remote store (prologue max-exchange only).
__device__ __forceinline__ void st_cluster_f32(uint32_t laddr, uint32_t rank, float v) {
    uint32_t rem = mapa_rank(laddr, rank);
    asm volatile("st.shared::cluster.f32 [%0], %1;" :: "r"(rem), "f"(v) : "memory");
}

// 1KB bulk copy: local SMEM -> (possibly remote) cluster SMEM, completion as
// a single complete_tx at the destination CTA's mbarrier.
__device__ __forceinline__ void bulk_s2s(uint32_t dst_cluster, uint32_t src_local,
                                         uint32_t bytes, uint32_t mbar_cluster) {
    asm volatile(
        "cp.async.bulk.shared::cluster.shared::cta.mbarrier::complete_tx::bytes "
        "[%0], [%1], %2, [%3];"
        :: "r"(dst_cluster), "r"(src_local), "r"(bytes), "r"(mbar_cluster) : "memory");
}

__device__ __forceinline__ void mbar_expect_tx(uint32_t addr, uint32_t bytes) {
    asm volatile("mbarrier.arrive.expect_tx.shared.b64 _, [%0], %1;"
                 :: "r"(addr), "r"(bytes) : "memory");
}

__device__ __forceinline__ void mbar_wait(uint32_t addr, uint32_t phase) {
    asm volatile(
        "{\n\t"
        ".reg .pred P;\n\t"
        "WLOOP_%=:\n\t"
        "mbarrier.try_wait.parity.acquire.cluster.shared::cta.b64 P, [%0], %1, 0x989680;\n\t"
        "@P bra WDONE_%=;\n\t"
        "bra WLOOP_%=;\n\t"
        "WDONE_%=:\n\t"
        "}"
        :: "r"(addr), "r"(phase) : "memory");
}

__device__ __forceinline__ void cluster_sync_all() {
    asm volatile("barrier.cluster.arrive.aligned;" ::: "memory");
    asm volatile("barrier.cluster.wait.aligned;" ::: "memory");
}

__global__ void __launch_bounds__(THREADS, 1) __cluster_dims__(CSZ, 1, 1)
sinkhorn_kernel(const float* __restrict__ A, float* __restrict__ Out)
{
    __shared__ __align__(16) float d_vec[N];
    __shared__ __align__(16) float e_vec[ROWS];
    // receive buffers: [parity][source rank][col]  (bulk copies land here)
    __shared__ __align__(16) float xbuf[2][CSZ][N];
    // staging buffer for my 256 column partials: [parity][col]
    __shared__ __align__(16) float pbuf[2][N];
    __shared__ __align__(8) unsigned long long mbar[2];
    __shared__ float red_sh[NWARP];
    __shared__ float mbuf[CSZ];

    const int tid  = threadIdx.x;
    const int w    = tid >> 5;
    const int l    = tid & 31;
    const int rank = blockIdx.x & (CSZ - 1);
    const int b    = blockIdx.x >> 2;

    const float* Am = A   + (size_t)b * N * N;
    float*       Om = Out + (size_t)b * N * N;

    if (tid == 0) {
        asm volatile("mbarrier.init.shared.b64 [%0], 1;" :: "r"(smem_u32(&mbar[0])) : "memory");
        asm volatile("mbarrier.init.shared.b64 [%0], 1;" :: "r"(smem_u32(&mbar[1])) : "memory");
        asm volatile("fence.mbarrier_init.release.cluster;" ::: "memory");
    }

    // ---- row layout: warp w owns local rows {2w, 2w+1}; lane l cols [8l,8l+8)
    const int r0   = 2 * w;            // local row index of first row
    const int c0   = l * 8;
    const int grow = rank * ROWS + r0; // global row of first row

    float er[16];  // [row 0: 8 cols][row 1: 8 cols]
    {
        float4 a0 = *(const float4*)(Am + grow * N + c0);
        float4 a1 = *(const float4*)(Am + grow * N + c0 + 4);
        float4 b0 = *(const float4*)(Am + (grow + 1) * N + c0);
        float4 b1 = *(const float4*)(Am + (grow + 1) * N + c0 + 4);
        er[0]=a0.x; er[1]=a0.y; er[2]=a0.z; er[3]=a0.w;
        er[4]=a1.x; er[5]=a1.y; er[6]=a1.z; er[7]=a1.w;
        er[8]=b0.x; er[9]=b0.y; er[10]=b0.z; er[11]=b0.w;
        er[12]=b1.x; er[13]=b1.y; er[14]=b1.z; er[15]=b1.w;
        #pragma unroll
        for (int k = 0; k < 16; k++) er[k] *= INV_TAU;
    }

    // ---- col layout: thread t = 4*j + g owns column j, local rows [16g,16g+16)
    const int jc = tid >> 2;
    const int g  = tid & 3;
    float ec[16];
    #pragma unroll
    for (int k = 0; k < 16; k++)
        ec[k] = Am[(rank * ROWS + g * 16 + k) * N + jc] * INV_TAU;

    // ---- global per-matrix max m (for stable E = exp(a/tau - m))
    float mx = er[0];
    #pragma unroll
    for (int k = 1; k < 16; k++) mx = fmaxf(mx, er[k]);
    #pragma unroll
    for (int off = 16; off; off >>= 1)
        mx = fmaxf(mx, __shfl_xor_sync(0xffffffffu, mx, off));
    if (l == 0) red_sh[w] = mx;
    __syncthreads();
    if (w == 0) {
        float v = red_sh[l];
        #pragma unroll
        for (int off = 16; off; off >>= 1)
            v = fmaxf(v, __shfl_xor_sync(0xffffffffu, v, off));
        if (l == 0) {
            uint32_t slot = smem_u32(&mbuf[rank]);
            #pragma unroll
            for (int r = 0; r < CSZ; r++) st_cluster_f32(slot, r, v);
        }
    }
    cluster_sync_all();   // orders mbuf stores AND mbarrier inits cluster-wide
    float m = mbuf[0];
    #pragma unroll
    for (int r = 1; r < CSZ; r++) m = fmaxf(m, mbuf[r]);

    // ---- E chunks in registers (both layouts)
    #pragma unroll
    for (int k = 0; k < 16; k++) er[k] = __expf(er[k] - m);
    #pragma unroll
    for (int k = 0; k < 16; k++) ec[k] = __expf(ec[k] - m);

    if (tid < N) d_vec[tid] = 1.0f;   // c = 0 initially
    __syncthreads();

    // ---- precomputed cluster addresses
    const uint32_t xb_local = smem_u32(&xbuf[0][0][0]);
    const uint32_t mb_local = smem_u32(&mbar[0]);
    const uint32_t pb_local = smem_u32(&pbuf[0][0]);
    uint32_t rxb[CSZ], rmb[CSZ];
    #pragma unroll
    for (int r = 0; r < CSZ; r++) {
        rxb[r] = mapa_rank(xb_local, (uint32_t)r);
        rmb[r] = mapa_rank(mb_local, (uint32_t)r);
    }
    const uint32_t my_slice_off = (uint32_t)rank * SLICE_BYTES;

    #pragma unroll 1
    for (int it = 0; it < NITER; it++) {
        const uint32_t par = (uint32_t)(it & 1);

        // ======== row pass: rowsum_i = sum_j E[i][j] * d[j] (2 rows/warp) ====
        float4 d0 = *(const float4*)&d_vec[c0];
        float4 d1 = *(const float4*)&d_vec[c0 + 4];
        float s0 = er[0]*d0.x + er[1]*d0.y + er[2]*d0.z + er[3]*d0.w
                 + er[4]*d1.x + er[5]*d1.y + er[6]*d1.z + er[7]*d1.w;
        float s1 = er[8]*d0.x + er[9]*d0.y + er[10]*d0.z + er[11]*d0.w
                 + er[12]*d1.x + er[13]*d1.y + er[14]*d1.z + er[15]*d1.w;
        #pragma unroll
        for (int off = 16; off; off >>= 1) {
            s0 += __shfl_xor_sync(0xffffffffu, s0, off);
            s1 += __shfl_xor_sync(0xffffffffu, s1, off);
        }
        if (l == 0) {
            e_vec[r0]     = __fdividef(1.0f, fmaxf(s0, 1e-30f));
            e_vec[r0 + 1] = __fdividef(1.0f, fmaxf(s1, 1e-30f));
        }
        __syncthreads();

        // ======== col pass: partial_j = sum_{local i} E[i][j] * e[i] ========
        float4 e0 = *(const float4*)&e_vec[g * 16];
        float4 e1 = *(const float4*)&e_vec[g * 16 + 4];
        float4 e2 = *(const float4*)&e_vec[g * 16 + 8];
        float4 e3 = *(const float4*)&e_vec[g * 16 + 12];
        float p = ec[0]*e0.x + ec[1]*e0.y + ec[2]*e0.z  + ec[3]*e0.w
                + ec[4]*e1.x + ec[5]*e1.y + ec[6]*e1.z  + ec[7]*e1.w
                + ec[8]*e2.x + ec[9]*e2.y + ec[10]*e2.z + ec[11]*e2.w
                + ec[12]*e3.x + ec[13]*e3.y + ec[14]*e3.z + ec[15]*e3.w;
        p += __shfl_xor_sync(0xffffffffu, p, 1);
        p += __shfl_xor_sync(0xffffffffu, p, 2);
        if (g == 0) pbuf[par][jc] = p;
        __syncthreads();   // pbuf[par] complete

        // ======== bulk exchange: 1KB to each cluster CTA ========
        if (tid == 0) {
            asm volatile("fence.proxy.async.shared::cta;" ::: "memory");
            mbar_expect_tx(mb_local + par * 8, TX_BYTES);
            uint32_t src  = pb_local + par * SLICE_BYTES;
            uint32_t doff = par * (CSZ * SLICE_BYTES) + my_slice_off;
            #pragma unroll
            for (int r = 0; r < CSZ; r++)
                bulk_s2s(rxb[r] + doff, src, SLICE_BYTES, rmb[r] + par * 8);
        }

        // ======== combine 4 partials -> d[j] ========
        if (tid < N) {
            mbar_wait(mb_local + par * 8, (uint32_t)((it >> 1) & 1));
            float f = xbuf[par][0][tid];
            #pragma unroll
            for (int r = 1; r < CSZ; r++) f += xbuf[par][r][tid];
            d_vec[tid] = __fdividef(1.0f, fmaxf(f, 1e-30f));
        }
        __syncthreads();
    }

    // ======== epilogue: P = E * e[i] * d[j] (2 rows/warp) ========
    {
        float ev0 = e_vec[r0];
        float ev1 = e_vec[r0 + 1];
        float4 d0 = *(const float4*)&d_vec[c0];
        float4 d1 = *(const float4*)&d_vec[c0 + 4];
        float4 o;
        o.x = er[0]*ev0*d0.x; o.y = er[1]*ev0*d0.y;
        o.z = er[2]*ev0*d0.z; o.w = er[3]*ev0*d0.w;
        *(float4*)(Om + grow * N + c0) = o;
        o.x = er[4]*ev0*d1.x; o.y = er[5]*ev0*d1.y;
        o.z = er[6]*ev0*d1.z; o.w = er[7]*ev0*d1.w;
        *(float4*)(Om + grow * N + c0 + 4) = o;
        o.x = er[8]*ev1*d0.x;  o.y = er[9]*ev1*d0.y;
        o.z = er[10]*ev1*d0.z; o.w = er[11]*ev1*d0.w;
        *(float4*)(Om + (grow + 1) * N + c0) = o;
        o.x = er[12]*ev1*d1.x; o.y = er[13]*ev1*d1.y;
        o.z = er[14]*ev1*d1.z; o.w = er[15]*ev1*d1.w;
        *(float4*)(Om + (grow + 1) * N + c0 + 4) = o;
    }

    // keep all CTAs alive until every in-flight bulk copy has been consumed
    cluster_sync_all();
}

extern "C" void kernel_launch(void* const* d_in, const int* in_sizes, int n_in,
                              void* d_out, int out_size) {
    const float* alpha = (const float*)d_in[0];
    float* out = (float*)d_out;
    sinkhorn_kernel<<<NMAT * CSZ, THREADS>>>(alpha, out);
}